// round 1
// baseline (speedup 1.0000x reference)
#include <cuda_runtime.h>
#include <cuda_bf16.h>
#include <stdint.h>

// out[token, :] = sign(weight[id, :]) * max(scales[id, col/128], 1e-8)
// ids: int32 [16384], weight: f32 [50257,1024], scales: f32 [50257,8]
// One block per token, 256 threads, one float4 (4 cols) per thread.

#define DIM 1024
#define GROUP 128
#define THREADS 256

__global__ __launch_bounds__(THREADS)
void literati_embed_kernel(const int* __restrict__ ids,
                           const float* __restrict__ weight,
                           const float* __restrict__ scales,
                           float* __restrict__ out)
{
    const int token = blockIdx.x;
    const int t = threadIdx.x;

    // All threads load the same id -> broadcast
    const int row = __ldg(&ids[token]);

    // Each thread covers cols [t*4, t*4+4). Group = (t*4)/128 = t>>5 (warp id)
    const int col = t * 4;
    const int g = t >> 5;  // warp-uniform

    float s = __ldg(&scales[(size_t)row * (DIM / GROUP) + g]);
    s = fmaxf(s, 1e-8f);

    const float4 w = *reinterpret_cast<const float4*>(
        &weight[(size_t)row * DIM + col]);

    float4 o;
    o.x = (w.x < 0.0f) ? -s : s;
    o.y = (w.y < 0.0f) ? -s : s;
    o.z = (w.z < 0.0f) ? -s : s;
    o.w = (w.w < 0.0f) ? -s : s;

    *reinterpret_cast<float4*>(&out[(size_t)token * DIM + col]) = o;
}

extern "C" void kernel_launch(void* const* d_in, const int* in_sizes, int n_in,
                              void* d_out, int out_size)
{
    const int* ids       = (const int*)d_in[0];
    const float* weight  = (const float*)d_in[1];
    const float* scales  = (const float*)d_in[2];
    float* out           = (float*)d_out;

    const int n_tokens = in_sizes[0];  // 8*2048 = 16384

    literati_embed_kernel<<<n_tokens, THREADS>>>(ids, weight, scales, out);
}

// round 2
// speedup vs baseline: 1.5405x; 1.5405x over previous
#include <cuda_runtime.h>
#include <cuda_bf16.h>
#include <stdint.h>

// out[token, :] = sign(weight[id, :]) * max(scales[id, col/128], 1e-8)
// ids: int32 [16384], weight: f32 [50257,1024], scales: f32 [50257,8]
//
// 8 tokens per block, 256 threads; thread t covers cols [4t, 4t+4) for
// all 8 tokens. All 8 weight float4 loads are issued independently before
// any use -> MLP ~8 per thread, hiding DRAM latency.

#define DIM 1024
#define GROUP 128
#define THREADS 256
#define TPB 8   // tokens per block

__global__ __launch_bounds__(THREADS)
void literati_embed_kernel(const int* __restrict__ ids,
                           const float* __restrict__ weight,
                           const float* __restrict__ scales,
                           float* __restrict__ out,
                           int n_tokens)
{
    const int t = threadIdx.x;
    const int col = t * 4;
    const int g = t >> 5;                 // group index, warp-uniform
    const int tok0 = blockIdx.x * TPB;

    // Load the 8 token ids (broadcast loads, L1-hit after first warp)
    int rows[TPB];
#pragma unroll
    for (int i = 0; i < TPB; i++) {
        int tok = tok0 + i;
        rows[i] = (tok < n_tokens) ? __ldg(&ids[tok]) : 0;
    }

    // Issue all scale loads (independent)
    float s[TPB];
#pragma unroll
    for (int i = 0; i < TPB; i++)
        s[i] = __ldg(&scales[(size_t)rows[i] * (DIM / GROUP) + g]);

    // Issue all weight loads (independent, front-batched for MLP)
    float4 w[TPB];
#pragma unroll
    for (int i = 0; i < TPB; i++)
        w[i] = *reinterpret_cast<const float4*>(
            &weight[(size_t)rows[i] * DIM + col]);

    // Compute + streaming store (output never re-read; keep L2 for weight)
#pragma unroll
    for (int i = 0; i < TPB; i++) {
        float sc = fmaxf(s[i], 1e-8f);
        float4 o;
        o.x = (w[i].x < 0.0f) ? -sc : sc;
        o.y = (w[i].y < 0.0f) ? -sc : sc;
        o.z = (w[i].z < 0.0f) ? -sc : sc;
        o.w = (w[i].w < 0.0f) ? -sc : sc;
        int tok = tok0 + i;
        if (tok < n_tokens)
            __stcs(reinterpret_cast<float4*>(&out[(size_t)tok * DIM + col]), o);
    }
}

extern "C" void kernel_launch(void* const* d_in, const int* in_sizes, int n_in,
                              void* d_out, int out_size)
{
    const int* ids       = (const int*)d_in[0];
    const float* weight  = (const float*)d_in[1];
    const float* scales  = (const float*)d_in[2];
    float* out           = (float*)d_out;

    const int n_tokens = in_sizes[0];  // 16384
    const int blocks = (n_tokens + TPB - 1) / TPB;

    literati_embed_kernel<<<blocks, THREADS>>>(ids, weight, scales, out, n_tokens);
}

// round 3
// speedup vs baseline: 1.5616x; 1.0137x over previous
#include <cuda_runtime.h>
#include <cuda_bf16.h>
#include <stdint.h>

// out[token, :] = sign(weight[id, :]) * max(scales[id, col/128], 1e-8)
// ids: int32 [16384], weight: f32 [50257,1024], scales: f32 [50257,8]
//
// cp.async pipelined gather: 16 tokens/block, 8-stage smem ring of 4KB
// weight rows. Loads live in smem (not registers) so pipeline depth is
// cheap; ~224KB in flight per SM hides L2/DRAM latency.

#define DIM     1024
#define NGROUP  8
#define THREADS 256
#define TPB     16   // tokens per block (16384/16 = 1024 blocks)
#define DEPTH   8    // pipeline stages (power of 2 -> cheap modulo)

__global__ __launch_bounds__(THREADS)
void literati_embed_kernel(const int* __restrict__ ids,
                           const float* __restrict__ weight,
                           const float* __restrict__ scales,
                           float* __restrict__ out,
                           int n_tokens)
{
    __shared__ __align__(16) float wbuf[DEPTH][DIM];
    __shared__ __align__(16) float sbuf[DEPTH][NGROUP];
    __shared__ int srows[TPB];

    const int t    = threadIdx.x;
    const int g    = t >> 5;          // scale group = warp id (warp-uniform)
    const int col  = t * 4;
    const int tok0 = blockIdx.x * TPB;

    if (t < TPB) {
        int tok = tok0 + t;
        srows[t] = (tok < n_tokens) ? ids[tok] : 0;
    }
    __syncthreads();

    // Issue stage i (or an empty group past the end to keep pending constant)
    auto issue = [&](int i) {
        if (i < TPB) {
            const int stage = i & (DEPTH - 1);
            const int row   = srows[i];
            const float* wsrc = weight + (size_t)row * DIM + col;
            uint32_t wdst = (uint32_t)__cvta_generic_to_shared(&wbuf[stage][col]);
            asm volatile("cp.async.cg.shared.global [%0], [%1], 16;\n"
                         :: "r"(wdst), "l"(wsrc));
            if (t < 2) {
                const float* ssrc = scales + (size_t)row * NGROUP + t * 4;
                uint32_t sdst = (uint32_t)__cvta_generic_to_shared(&sbuf[stage][t * 4]);
                asm volatile("cp.async.cg.shared.global [%0], [%1], 16;\n"
                             :: "r"(sdst), "l"(ssrc));
            }
        }
        asm volatile("cp.async.commit_group;\n");
    };

    // Prologue: fill the pipeline
#pragma unroll
    for (int i = 0; i < DEPTH; ++i) issue(i);

    for (int c = 0; c < TPB; ++c) {
        // Pending is always DEPTH groups; this completes the oldest (stage c)
        asm volatile("cp.async.wait_group %0;\n" :: "n"(DEPTH - 1));
        __syncthreads();

        const int stage = c & (DEPTH - 1);
        float s = fmaxf(sbuf[stage][g], 1e-8f);
        float4 w = *reinterpret_cast<const float4*>(&wbuf[stage][col]);

        float4 o;
        o.x = (w.x < 0.0f) ? -s : s;
        o.y = (w.y < 0.0f) ? -s : s;
        o.z = (w.z < 0.0f) ? -s : s;
        o.w = (w.w < 0.0f) ? -s : s;

        const int tok = tok0 + c;
        if (tok < n_tokens)
            __stcs(reinterpret_cast<float4*>(&out[(size_t)tok * DIM + col]), o);

        __syncthreads();     // everyone done with this stage before refill
        issue(c + DEPTH);    // empty commit_group past the end
    }
}

extern "C" void kernel_launch(void* const* d_in, const int* in_sizes, int n_in,
                              void* d_out, int out_size)
{
    const int* ids      = (const int*)d_in[0];
    const float* weight = (const float*)d_in[1];
    const float* scales = (const float*)d_in[2];
    float* out          = (float*)d_out;

    const int n_tokens = in_sizes[0];  // 16384
    const int blocks = (n_tokens + TPB - 1) / TPB;

    literati_embed_kernel<<<blocks, THREADS>>>(ids, weight, scales, out, n_tokens);
}

// round 4
// speedup vs baseline: 1.5697x; 1.0052x over previous
#include <cuda_runtime.h>
#include <cuda_bf16.h>
#include <stdint.h>

// out[token, :] = sign(weight[id, :]) * max(scales[id, col/128], 1e-8)
// ids: int32 [16384], weight: f32 [50257,1024], scales: f32 [50257,8]
//
// Warp-private cp.async pipeline: each warp owns a 2-stage ring of 4KB row
// buffers. No __syncthreads in the loop; each lane reads back exactly the
// smem bytes its own cp.async wrote, so only the tiny scale buffer needs a
// __syncwarp. Lane l covers bytes [j*512 + l*16) of the row for j=0..7,
// making global loads, smem accesses and stores all coalesced; the scale
// group index is simply j (warp-uniform broadcast).

#define DIM       1024
#define NGROUP    8
#define THREADS   128
#define NW        4          // warps per block
#define DEPTH     2          // pipeline stages per warp
#define RPW       8          // rows (tokens) per warp
#define TPB       (NW * RPW) // 32 tokens per block

__global__ __launch_bounds__(THREADS)
void literati_embed_kernel(const int* __restrict__ ids,
                           const float* __restrict__ weight,
                           const float* __restrict__ scales,
                           float* __restrict__ out,
                           int n_tokens)
{
    __shared__ __align__(16) float wbuf[NW][DEPTH][DIM];     // 32 KB
    __shared__ __align__(16) float sbuf[NW][DEPTH][NGROUP];  // 256 B
    __shared__ int srows[TPB];

    const int t    = threadIdx.x;
    const int wid  = t >> 5;
    const int ln   = t & 31;
    const int tok0 = blockIdx.x * TPB;

    if (t < TPB) {
        int tok = tok0 + t;
        srows[t] = (tok < n_tokens) ? ids[tok] : 0;
    }
    __syncthreads();  // only sync in the kernel

    // Issue pipeline stage for this warp's row r (empty commit past the end)
    auto issue = [&](int r) {
        if (r < RPW) {
            const int stage = r & (DEPTH - 1);
            const int row   = srows[wid * RPW + r];
            const float* src = weight + (size_t)row * DIM;
#pragma unroll
            for (int j = 0; j < 8; j++) {
                uint32_t dst = (uint32_t)__cvta_generic_to_shared(
                    &wbuf[wid][stage][j * 128 + ln * 4]);
                asm volatile("cp.async.cg.shared.global [%0], [%1], 16;\n"
                             :: "r"(dst), "l"(src + j * 128 + ln * 4));
            }
            if (ln < 2) {
                uint32_t dst = (uint32_t)__cvta_generic_to_shared(
                    &sbuf[wid][stage][ln * 4]);
                asm volatile("cp.async.cg.shared.global [%0], [%1], 16;\n"
                             :: "r"(dst), "l"(scales + (size_t)row * NGROUP + ln * 4));
            }
        }
        asm volatile("cp.async.commit_group;\n");
    };

    // Prologue
#pragma unroll
    for (int r = 0; r < DEPTH; r++) issue(r);

    for (int r = 0; r < RPW; r++) {
        asm volatile("cp.async.wait_group %0;\n" :: "n"(DEPTH - 1));
        __syncwarp();  // make lane0/1's sbuf visible to all lanes

        const int stage = r & (DEPTH - 1);
        const int tok   = tok0 + wid * RPW + r;
        float4* orow = reinterpret_cast<float4*>(out + (size_t)tok * DIM);

#pragma unroll
        for (int j = 0; j < 8; j++) {
            float s = fmaxf(sbuf[wid][stage][j], 1e-8f);  // broadcast, conflict-free
            float4 w = *reinterpret_cast<const float4*>(
                &wbuf[wid][stage][j * 128 + ln * 4]);
            float4 o;
            o.x = (w.x < 0.0f) ? -s : s;
            o.y = (w.y < 0.0f) ? -s : s;
            o.z = (w.z < 0.0f) ? -s : s;
            o.w = (w.w < 0.0f) ? -s : s;
            if (tok < n_tokens)
                __stcs(&orow[j * 32 + ln], o);
        }

        __syncwarp();      // all lanes done reading sbuf[stage] before refill
        issue(r + DEPTH);
    }
}

extern "C" void kernel_launch(void* const* d_in, const int* in_sizes, int n_in,
                              void* d_out, int out_size)
{
    const int* ids      = (const int*)d_in[0];
    const float* weight = (const float*)d_in[1];
    const float* scales = (const float*)d_in[2];
    float* out          = (float*)d_out;

    const int n_tokens = in_sizes[0];  // 16384
    const int blocks = (n_tokens + TPB - 1) / TPB;

    literati_embed_kernel<<<blocks, THREADS>>>(ids, weight, scales, out, n_tokens);
}